// round 14
// baseline (speedup 1.0000x reference)
#include <cuda_runtime.h>
#include <cuda_fp16.h>

// Sinkhorn on s[B=32, N=1024, M=1024], MAX_ITER=15, EPS=1e-4.
//
// Single persistent kernel (R13 + chunked row/col fusion for L1 reuse).
// Factored form s_t = r_i * s0_ij * c_j. Batch = CGA cluster of 8 CTAs,
// hardware cluster barriers. Block k owns rows [128k,128k+128).
//
// Each of the 7 fused iterations processes its 128 rows in 4 chunks of 32:
//   row-step the chunk (reads populate L1), __syncthreads,
//   col-accumulate the SAME chunk (L1 hits) into per-thread smem slots.
// This halves the loop's L2 traffic vs separate row/col sweeps.

#define BB 32
#define NN 1024
#define MM 1024
#define EPSF 1e-4f
#define KB_ 8             // blocks per batch = cluster size
#define RPB (NN / KB_)    // 128 rows per block
#define HROWS 64          // rows per half (conv/finalize split)
#define TPB 512

__device__ __half2 g_h[(size_t)BB * NN * MM / 2];   // 64 MB fp16 copy
__device__ float g_part[2][BB * KB_ * MM];          // double-buffered partials

__device__ __forceinline__ void cluster_barrier() {
    asm volatile("barrier.cluster.arrive.aligned;" ::: "memory");
    asm volatile("barrier.cluster.wait.aligned;" ::: "memory");
}

// ---------------------------------------------------------------------------
__global__ void __launch_bounds__(TPB, 2) __cluster_dims__(KB_, 1, 1)
sinkhorn_kernel(const float* __restrict__ s, float* __restrict__ out) {
    const int bx = blockIdx.x;
    const int b = bx >> 3;         // batch (== cluster id)
    const int k = bx & (KB_ - 1);  // block within batch (== cluster rank)
    const int tid = threadIdx.x;
    const int half = tid >> 8;     // 0 or 1
    const int ct = tid & 255;      // column group: owns cols [4ct, 4ct+4)
    const int warp = tid >> 5;     // 0..15
    const int lane = tid & 31;

    __shared__ __align__(16) float sc[MM];        // column scaling c
    __shared__ float sr[RPB];                     // row scaling r
    __shared__ __align__(16) float scomb[MM];     // half-combine (c update)
    __shared__ __align__(16) float spart[TPB*4];  // per-thread col partials

    const size_t hrow0 = (size_t)(b * NN + k * RPB + half * HROWS);
    const size_t brow0 = (size_t)(b * NN + k * RPB);

    // ---------------- it = 0: fp32->fp16 conversion + column partials (r=1)
    {
        const float4* sp = (const float4*)(s + hrow0 * MM) + ct;
        __half2* hp = g_h + hrow0 * (MM / 2) + ct * 2;
        float4 acc = make_float4(0.f, 0.f, 0.f, 0.f);
#pragma unroll 4
        for (int i = 0; i < HROWS; i++) {
            float4 v = sp[(size_t)i * (MM / 4)];
            __half2 h0 = __floats2half2_rn(v.x, v.y);
            __half2 h1 = __floats2half2_rn(v.z, v.w);
            uint2 o;
            o.x = *(unsigned*)&h0;
            o.y = *(unsigned*)&h1;
            *(uint2*)(hp + (size_t)i * (MM / 2)) = o;
            acc.x += v.x; acc.y += v.y; acc.z += v.z; acc.w += v.w;
        }
        if (half) *(float4*)&scomb[ct * 4] = acc;
        __syncthreads();
        if (!half) {
            float4 o2 = *(float4*)&scomb[ct * 4];
            acc.x += o2.x; acc.y += o2.y; acc.z += o2.z; acc.w += o2.w;
            *(float4*)&g_part[0][((size_t)(b * KB_ + k)) * MM + ct * 4] = acc;
        }
    }
    cluster_barrier();

    // c init (c_old = 1): split reduce across halves.
    {
        const int j = ct * 4;
        float4 p = make_float4(0.f, 0.f, 0.f, 0.f);
#pragma unroll
        for (int q = 0; q < KB_ / 2; q++) {
            const int qq = half * (KB_ / 2) + q;
            const float4 v = __ldcg(
                (const float4*)&g_part[0][((size_t)(b * KB_ + qq)) * MM + j]);
            p.x += v.x; p.y += v.y; p.z += v.z; p.w += v.w;
        }
        if (half) *(float4*)&scomb[j] = p;
        __syncthreads();
        if (!half) {
            float4 o2 = *(float4*)&scomb[j];
            p.x += o2.x; p.y += o2.y; p.z += o2.z; p.w += o2.w;
            sc[j + 0] = 1.0f / (p.x + EPSF);
            sc[j + 1] = 1.0f / (p.y + EPSF);
            sc[j + 2] = 1.0f / (p.z + EPSF);
            sc[j + 3] = 1.0f / (p.w + EPSF);
        }
    }
    __syncthreads();

    // ---------------- 7 x fused (row it=2h+1 + col it=2h+2), chunked by 32
    for (int hh = 0; hh < 7; hh++) {
        *(float4*)&spart[tid * 4] = make_float4(0.f, 0.f, 0.f, 0.f);

#pragma unroll 1
        for (int cc = 0; cc < RPB / 32; cc++) {
            const int rb = cc * 32;

            // ---- row step: warp w handles rows rb+2w, rb+2w+1
            {
                const int i0 = rb + warp * 2;
                const uint4* hpa =
                    (const uint4*)(g_h + (brow0 + i0) * (MM / 2));
                const uint4* hpb = hpa + (MM / 8);
                float qa = 0.f, qb = 0.f;
#pragma unroll
                for (int kk = 0; kk < 4; kk++) {
                    const int v4 = kk * 32 + lane;
                    uint4 va = hpa[v4];
                    uint4 vb = hpb[v4];
                    const int jj = v4 * 8;
                    float2 a0 = __half22float2(*(__half2*)&va.x);
                    float2 a1 = __half22float2(*(__half2*)&va.y);
                    float2 a2 = __half22float2(*(__half2*)&va.z);
                    float2 a3 = __half22float2(*(__half2*)&va.w);
                    float2 b0 = __half22float2(*(__half2*)&vb.x);
                    float2 b1 = __half22float2(*(__half2*)&vb.y);
                    float2 b2 = __half22float2(*(__half2*)&vb.z);
                    float2 b3 = __half22float2(*(__half2*)&vb.w);
                    qa = fmaf(a0.x, sc[jj + 0], qa);
                    qb = fmaf(b0.x, sc[jj + 0], qb);
                    qa = fmaf(a0.y, sc[jj + 1], qa);
                    qb = fmaf(b0.y, sc[jj + 1], qb);
                    qa = fmaf(a1.x, sc[jj + 2], qa);
                    qb = fmaf(b1.x, sc[jj + 2], qb);
                    qa = fmaf(a1.y, sc[jj + 3], qa);
                    qb = fmaf(b1.y, sc[jj + 3], qb);
                    qa = fmaf(a2.x, sc[jj + 4], qa);
                    qb = fmaf(b2.x, sc[jj + 4], qb);
                    qa = fmaf(a2.y, sc[jj + 5], qa);
                    qb = fmaf(b2.y, sc[jj + 5], qb);
                    qa = fmaf(a3.x, sc[jj + 6], qa);
                    qb = fmaf(b3.x, sc[jj + 6], qb);
                    qa = fmaf(a3.y, sc[jj + 7], qa);
                    qb = fmaf(b3.y, sc[jj + 7], qb);
                }
#pragma unroll
                for (int o = 16; o > 0; o >>= 1) {
                    qa += __shfl_xor_sync(0xffffffffu, qa, o);
                    qb += __shfl_xor_sync(0xffffffffu, qb, o);
                }
                if (lane == 0) {
                    float r0 = (hh == 0) ? 1.0f : sr[i0];
                    float r1 = (hh == 0) ? 1.0f : sr[i0 + 1];
                    sr[i0] = r0 / fmaf(r0, qa, EPSF);
                    sr[i0 + 1] = r1 / fmaf(r1, qb, EPSF);
                }
            }
            __syncthreads();

            // ---- col accumulate: half h covers rows [rb+16h, rb+16h+16)
            // (same lines just read by the row step -> L1 hits)
            {
                const size_t r0g = brow0 + rb + half * 16;
                const uint2* hp = (const uint2*)(g_h + r0g * (MM / 2)) + ct;
                const float* srh = sr + rb + half * 16;
                float4 a = make_float4(0.f, 0.f, 0.f, 0.f);
#pragma unroll 8
                for (int i = 0; i < 16; i++) {
                    uint2 v = hp[(size_t)i * (MM / 4)];
                    float rw = srh[i];
                    float2 f0 = __half22float2(*(__half2*)&v.x);
                    float2 f1 = __half22float2(*(__half2*)&v.y);
                    a.x = fmaf(rw, f0.x, a.x);
                    a.y = fmaf(rw, f0.y, a.y);
                    a.z = fmaf(rw, f1.x, a.z);
                    a.w = fmaf(rw, f1.y, a.w);
                }
                float4 t = *(float4*)&spart[tid * 4];
                t.x += a.x; t.y += a.y; t.z += a.z; t.w += a.w;
                *(float4*)&spart[tid * 4] = t;
            }
            // no sync: next chunk's row step touches disjoint sr rows
        }
        __syncthreads();  // spart complete before cross-half combine

        const int buf = (hh + 1) & 1;
        if (!half) {
            float4 p0 = *(float4*)&spart[ct * 4];
            float4 p1 = *(float4*)&spart[(256 + ct) * 4];
            p0.x += p1.x; p0.y += p1.y; p0.z += p1.z; p0.w += p1.w;
            *(float4*)&g_part[buf][((size_t)(b * KB_ + k)) * MM + ct * 4] = p0;
        }
        cluster_barrier();

        // ---- reduce partials -> c update (per block; split across halves)
        {
            const int j = ct * 4;
            float4 p = make_float4(0.f, 0.f, 0.f, 0.f);
#pragma unroll
            for (int q = 0; q < KB_ / 2; q++) {
                const int qq = half * (KB_ / 2) + q;
                const float4 v = __ldcg((const float4*)
                    &g_part[buf][((size_t)(b * KB_ + qq)) * MM + j]);
                p.x += v.x; p.y += v.y; p.z += v.z; p.w += v.w;
            }
            if (half) *(float4*)&scomb[j] = p;
            __syncthreads();
            if (!half) {
                float4 o2 = *(float4*)&scomb[j];
                p.x += o2.x; p.y += o2.y; p.z += o2.z; p.w += o2.w;
                float4 c = *(float4*)&sc[j];
                c.x = c.x / fmaf(c.x, p.x, EPSF);
                c.y = c.y / fmaf(c.y, p.y, EPSF);
                c.z = c.z / fmaf(c.z, p.z, EPSF);
                c.w = c.w / fmaf(c.w, p.w, EPSF);
                *(float4*)&sc[j] = c;
            }
        }
        __syncthreads();
    }

    // ---------------- finalize: out = r_i * h_ij * c_j (fp16 copy, L2-hot)
    {
        const int j = ct * 4;
        const float4 c4 = *(float4*)&sc[j];
        const float* srh = sr + half * HROWS;
        const uint2* hp = (const uint2*)(g_h + hrow0 * (MM / 2)) + ct;
        float4* op = (float4*)(out + hrow0 * MM) + ct;
#pragma unroll 4
        for (int i = 0; i < HROWS; i++) {
            const float r = srh[i];
            uint2 v = hp[(size_t)i * (MM / 4)];
            float2 f0 = __half22float2(*(__half2*)&v.x);
            float2 f1 = __half22float2(*(__half2*)&v.y);
            float4 o;
            o.x = r * f0.x * c4.x;
            o.y = r * f0.y * c4.y;
            o.z = r * f1.x * c4.z;
            o.w = r * f1.y * c4.w;
            op[(size_t)i * (MM / 4)] = o;
        }
    }
}

// ---------------------------------------------------------------------------
extern "C" void kernel_launch(void* const* d_in, const int* in_sizes, int n_in,
                              void* d_out, int out_size) {
    const float* s = (const float*)d_in[0];
    float* out = (float*)d_out;
    sinkhorn_kernel<<<BB * KB_, TPB>>>(s, out);
}

// round 15
// speedup vs baseline: 1.0609x; 1.0609x over previous
#include <cuda_runtime.h>
#include <cuda_fp16.h>

// Sinkhorn on s[B=32, N=1024, M=1024], MAX_ITER=15, EPS=1e-4.
//
// Single persistent kernel (R13 base). Factored form s_t = r_i*s0_ij*c_j.
// Batch = CGA cluster of 8 CTAs; block k owns rows [128k,128k+128); halves
// own 64 rows each. Sweep bodies identical to R13 (best validated).
//
// R15 delta: the per-iteration c-exchange no longer round-trips through L2.
// Column partials are scattered directly into the owning rank's smem via
// mapa + st.shared::cluster (DSMEM); rank k reduces its 128-col slice
// locally (c_old lives in registers of warp 0) and broadcasts the updated
// slice into every CTA's sc[] via DSMEM. Two cluster barriers bracket each
// exchange, which also makes the single-buffered recv[] race-free.

#define BB 32
#define NN 1024
#define MM 1024
#define EPSF 1e-4f
#define KB_ 8             // blocks per batch = cluster size
#define RPB (NN / KB_)    // 128 rows per block
#define HROWS 64          // rows per half
#define TPB 512

__device__ __half2 g_h[(size_t)BB * NN * MM / 2];   // 64 MB fp16 copy

__device__ __forceinline__ void cluster_barrier() {
    asm volatile("barrier.cluster.arrive.aligned;" ::: "memory");
    asm volatile("barrier.cluster.wait.aligned;" ::: "memory");
}

__device__ __forceinline__ unsigned smem_u32(const void* p) {
    return (unsigned)__cvta_generic_to_shared(p);
}

// store float4 into CTA `rank`'s shared memory at the same local offset
__device__ __forceinline__ void sts_cluster_v4(unsigned laddr, int rank,
                                               float4 v) {
    unsigned raddr;
    asm volatile("mapa.shared::cluster.u32 %0, %1, %2;"
                 : "=r"(raddr) : "r"(laddr), "r"(rank));
    asm volatile("st.shared::cluster.v4.f32 [%0], {%1, %2, %3, %4};"
                 :: "r"(raddr), "f"(v.x), "f"(v.y), "f"(v.z), "f"(v.w)
                 : "memory");
}

// ---------------------------------------------------------------------------
__global__ void __launch_bounds__(TPB, 2) __cluster_dims__(KB_, 1, 1)
sinkhorn_kernel(const float* __restrict__ s, float* __restrict__ out) {
    const int bx = blockIdx.x;
    const int b = bx >> 3;         // batch (== cluster id)
    const int k = bx & (KB_ - 1);  // rank within cluster
    const int tid = threadIdx.x;
    const int half = tid >> 8;     // 0 or 1
    const int ct = tid & 255;      // column group: owns cols [4ct, 4ct+4)

    __shared__ float sc[MM];            // column scaling c (full vector)
    __shared__ float sr[RPB];           // row scaling r (own 128 rows)
    __shared__ float scomb[MM];         // half-combine buffer (4 KB)
    __shared__ float recv[KB_ * 128];   // partial slices from 8 ranks (4 KB)

    const size_t hrow0 = (size_t)(b * NN + k * RPB + half * HROWS);
    const size_t brow0 = (size_t)(b * NN + k * RPB);

    float4 creg;  // c slice owned by warp 0 threads 0..31 (4 cols each)

    // ---------------- it = 0: fp32->fp16 conversion + column partials (r=1)
    {
        const float4* sp = (const float4*)(s + hrow0 * MM) + ct;
        __half2* hp = g_h + hrow0 * (MM / 2) + ct * 2;
        float4 acc = make_float4(0.f, 0.f, 0.f, 0.f);
#pragma unroll 4
        for (int i = 0; i < HROWS; i++) {
            float4 v = sp[(size_t)i * (MM / 4)];
            __half2 h0 = __floats2half2_rn(v.x, v.y);
            __half2 h1 = __floats2half2_rn(v.z, v.w);
            uint2 o;
            o.x = *(unsigned*)&h0;
            o.y = *(unsigned*)&h1;
            *(uint2*)(hp + (size_t)i * (MM / 2)) = o;
            acc.x += v.x; acc.y += v.y; acc.z += v.z; acc.w += v.w;
        }
        if (half) *(float4*)&scomb[ct * 4] = acc;
        __syncthreads();
        if (!half) {
            float4 o2 = *(float4*)&scomb[ct * 4];
            acc.x += o2.x; acc.y += o2.y; acc.z += o2.z; acc.w += o2.w;
            // scatter: cols [4ct,4ct+4) belong to rank ct>>5
            unsigned laddr = smem_u32(&recv[k * 128 + (ct & 31) * 4]);
            sts_cluster_v4(laddr, ct >> 5, acc);
        }
    }
    cluster_barrier();

    // c init (c_old = 1): rank k reduces its 128-col slice, broadcasts.
    if (tid < 32) {
        float4 p = make_float4(0.f, 0.f, 0.f, 0.f);
#pragma unroll
        for (int q = 0; q < KB_; q++) {
            float4 v = *(float4*)&recv[q * 128 + tid * 4];
            p.x += v.x; p.y += v.y; p.z += v.z; p.w += v.w;
        }
        creg.x = 1.0f / (p.x + EPSF);
        creg.y = 1.0f / (p.y + EPSF);
        creg.z = 1.0f / (p.z + EPSF);
        creg.w = 1.0f / (p.w + EPSF);
        unsigned laddr = smem_u32(&sc[k * 128 + tid * 4]);
#pragma unroll
        for (int r = 0; r < KB_; r++) sts_cluster_v4(laddr, r, creg);
    }
    cluster_barrier();

    // ---------------- 7 x (row step it=2h+1, col step it=2h+2)
    const int warp = tid >> 5;     // 0..15
    const int lane = tid & 31;

    for (int hh = 0; hh < 7; hh++) {
        // ---- row step: warp w handles rows [8w, 8w+8) of the 128-row slice
#pragma unroll
        for (int rr = 0; rr < RPB / 16; rr++) {   // 8 rows per warp
            const int i = warp * (RPB / 16) + rr;
            const uint4* hp = (const uint4*)(g_h + (brow0 + i) * (MM / 2));
            float acc = 0.f;
#pragma unroll
            for (int kk = 0; kk < 4; kk++) {
                int v4 = kk * 32 + lane;
                uint4 v = hp[v4];
                int jj = v4 * 8;
                float2 f0 = __half22float2(*(__half2*)&v.x);
                float2 f1 = __half22float2(*(__half2*)&v.y);
                float2 f2 = __half22float2(*(__half2*)&v.z);
                float2 f3 = __half22float2(*(__half2*)&v.w);
                acc = fmaf(f0.x, sc[jj + 0], acc);
                acc = fmaf(f0.y, sc[jj + 1], acc);
                acc = fmaf(f1.x, sc[jj + 2], acc);
                acc = fmaf(f1.y, sc[jj + 3], acc);
                acc = fmaf(f2.x, sc[jj + 4], acc);
                acc = fmaf(f2.y, sc[jj + 5], acc);
                acc = fmaf(f3.x, sc[jj + 6], acc);
                acc = fmaf(f3.y, sc[jj + 7], acc);
            }
#pragma unroll
            for (int o = 16; o > 0; o >>= 1)
                acc += __shfl_xor_sync(0xffffffffu, acc, o);
            if (lane == 0) {
                float r = (hh == 0) ? 1.0f : sr[i];
                sr[i] = r / fmaf(r, acc, EPSF);
            }
        }
        __syncthreads();

        // ---- col step partials: P_j += r_i * h_ij over this half's 64 rows
        {
            const uint2* hp = (const uint2*)(g_h + hrow0 * (MM / 2)) + ct;
            const float* srh = sr + half * HROWS;
            float4 acc = make_float4(0.f, 0.f, 0.f, 0.f);
#pragma unroll 8
            for (int i = 0; i < HROWS; i++) {
                uint2 v = hp[(size_t)i * (MM / 4)];
                float rw = srh[i];
                float2 f0 = __half22float2(*(__half2*)&v.x);
                float2 f1 = __half22float2(*(__half2*)&v.y);
                acc.x = fmaf(rw, f0.x, acc.x);
                acc.y = fmaf(rw, f0.y, acc.y);
                acc.z = fmaf(rw, f1.x, acc.z);
                acc.w = fmaf(rw, f1.y, acc.w);
            }
            if (half) *(float4*)&scomb[ct * 4] = acc;
            __syncthreads();
            if (!half) {
                float4 o2 = *(float4*)&scomb[ct * 4];
                acc.x += o2.x; acc.y += o2.y; acc.z += o2.z; acc.w += o2.w;
                unsigned laddr = smem_u32(&recv[k * 128 + (ct & 31) * 4]);
                sts_cluster_v4(laddr, ct >> 5, acc);
            }
        }
        cluster_barrier();

        // ---- slice reduce + c update in registers + DSMEM broadcast
        if (tid < 32) {
            float4 p = make_float4(0.f, 0.f, 0.f, 0.f);
#pragma unroll
            for (int q = 0; q < KB_; q++) {
                float4 v = *(float4*)&recv[q * 128 + tid * 4];
                p.x += v.x; p.y += v.y; p.z += v.z; p.w += v.w;
            }
            creg.x = creg.x / fmaf(creg.x, p.x, EPSF);
            creg.y = creg.y / fmaf(creg.y, p.y, EPSF);
            creg.z = creg.z / fmaf(creg.z, p.z, EPSF);
            creg.w = creg.w / fmaf(creg.w, p.w, EPSF);
            unsigned laddr = smem_u32(&sc[k * 128 + tid * 4]);
#pragma unroll
            for (int r = 0; r < KB_; r++) sts_cluster_v4(laddr, r, creg);
        }
        cluster_barrier();
    }

    // ---------------- finalize: out = r_i * h_ij * c_j (fp16 copy, L2-hot)
    {
        const int j = ct * 4;
        const float4 c4 = *(float4*)&sc[j];
        const float* srh = sr + half * HROWS;
        const uint2* hp = (const uint2*)(g_h + hrow0 * (MM / 2)) + ct;
        float4* op = (float4*)(out + hrow0 * MM) + ct;
#pragma unroll 4
        for (int i = 0; i < HROWS; i++) {
            const float r = srh[i];
            uint2 v = hp[(size_t)i * (MM / 4)];
            float2 f0 = __half22float2(*(__half2*)&v.x);
            float2 f1 = __half22float2(*(__half2*)&v.y);
            float4 o;
            o.x = r * f0.x * c4.x;
            o.y = r * f0.y * c4.y;
            o.z = r * f1.x * c4.z;
            o.w = r * f1.y * c4.w;
            op[(size_t)i * (MM / 4)] = o;
        }
    }
}

// ---------------------------------------------------------------------------
extern "C" void kernel_launch(void* const* d_in, const int* in_sizes, int n_in,
                              void* d_out, int out_size) {
    const float* s = (const float*)d_in[0];
    float* out = (float*)d_out;
    sinkhorn_kernel<<<BB * KB_, TPB>>>(s, out);
}